// round 1
// baseline (speedup 1.0000x reference)
#include <cuda_runtime.h>
#include <math_constants.h>

#define N_PTS 16384
#define C_DIM 256
#define KNN   32
#define QPB   16
#define CAP   256
#define RAD2  0.09f

// ---------------- scratch (no allocations allowed) ----------------
__device__ int   g_nbr[N_PTS * KNN];        // 2 MB
__device__ float g_pooled[N_PTS * C_DIM];   // 16 MB
__device__ float g_Wt[C_DIM * C_DIM];       // 256 KB (W transposed, k-major)

// ---------------- kernel 1: ball query (exact top-32 set) ----------------
__global__ void __launch_bounds__(256)
ball_query_kernel(const float* __restrict__ pts)
{
    __shared__ float sqx[QPB], sqy[QPB], sqz[QPB];
    __shared__ int   scnt[QPB];
    __shared__ int   sidx[QPB][CAP];
    __shared__ float sd2[QPB][CAP];
    __shared__ float sp[3 * 256];

    const int tid = threadIdx.x;
    const int q0  = blockIdx.x * QPB;

    if (tid < QPB) {
        sqx[tid] = pts[(q0 + tid) * 3 + 0];
        sqy[tid] = pts[(q0 + tid) * 3 + 1];
        sqz[tid] = pts[(q0 + tid) * 3 + 2];
        scnt[tid] = 0;
    }
    __syncthreads();

    float qx[QPB], qy[QPB], qz[QPB];
#pragma unroll
    for (int q = 0; q < QPB; q++) { qx[q] = sqx[q]; qy[q] = sqy[q]; qz[q] = sqz[q]; }

    for (int base = 0; base < N_PTS; base += 256) {
        // coalesced stage of 256 points (768 floats)
        sp[tid]       = pts[base * 3 + tid];
        sp[tid + 256] = pts[base * 3 + tid + 256];
        sp[tid + 512] = pts[base * 3 + tid + 512];
        __syncthreads();

        const float px = sp[3 * tid];      // stride-3 across lanes: conflict-free
        const float py = sp[3 * tid + 1];
        const float pz = sp[3 * tid + 2];
        const int j = base + tid;
#pragma unroll
        for (int q = 0; q < QPB; q++) {
            float dx = px - qx[q];
            float dy = py - qy[q];
            float dz = pz - qz[q];
            float d2 = fmaf(dx, dx, fmaf(dy, dy, dz * dz));
            if (d2 <= RAD2) {
                int pos = atomicAdd(&scnt[q], 1);
                if (pos < CAP) { sidx[q][pos] = j; sd2[q][pos] = d2; }
            }
        }
        __syncthreads();
    }

    // selection: one warp per query
    const int lane = tid & 31;
    const int warp = tid >> 5;
    for (int q = warp; q < QPB; q += 8) {
        int c = min(scnt[q], CAP);
        const int qid = q0 + q;
        if (c <= KNN) {
            // all in-radius candidates + index-0 padding (set semantics)
            nbr_write:
            if (lane < KNN)
                g_nbr[qid * KNN + lane] = (lane < c) ? sidx[q][lane] : 0;
        } else {
            // 32 rounds of warp-argmin on packed (d2_bits, slot) keys
            for (int r = 0; r < KNN; r++) {
                unsigned long long best = ~0ull;
                for (int t = lane; t < c; t += 32) {
                    unsigned long long key =
                        ((unsigned long long)__float_as_uint(sd2[q][t]) << 32) |
                        (unsigned int)t;
                    if (key < best) best = key;
                }
#pragma unroll
                for (int off = 16; off; off >>= 1) {
                    unsigned long long o = __shfl_xor_sync(0xffffffffu, best, off);
                    if (o < best) best = o;
                }
                int pos = (int)(best & 0xffffffffu);
                if (lane == 0) {
                    g_nbr[qid * KNN + r] = sidx[q][pos];
                    sd2[q][pos] = CUDART_INF_F;   // remove from next rounds
                }
                __syncwarp();
            }
        }
    }
}

// ---------------- kernel 2: gather + max-pool ----------------
__global__ void __launch_bounds__(256)
maxpool_kernel(const float* __restrict__ feats)
{
    __shared__ int s[KNN];
    const int q = blockIdx.x;
    const int tid = threadIdx.x;
    if (tid < KNN) s[tid] = g_nbr[q * KNN + tid];
    __syncthreads();

    float m = -CUDART_INF_F;
#pragma unroll
    for (int k = 0; k < KNN; k++)
        m = fmaxf(m, __ldg(&feats[(size_t)s[k] * C_DIM + tid]));
    g_pooled[q * C_DIM + tid] = m;
}

// ---------------- kernel 3: W transpose (so GEMM B-loads coalesce) ----------------
__global__ void transpose_kernel(const float* __restrict__ W)
{
    __shared__ float t[32][33];
    const int bx = blockIdx.x * 32, by = blockIdx.y * 32;
    const int x = threadIdx.x, y = threadIdx.y;   // block (32,8)
#pragma unroll
    for (int i = 0; i < 32; i += 8)
        t[y + i][x] = W[(by + y + i) * C_DIM + bx + x];
    __syncthreads();
#pragma unroll
    for (int i = 0; i < 32; i += 8)
        g_Wt[(bx + y + i) * C_DIM + by + x] = t[x][y + i];
}

// ---------------- kernel 4: GEMM (h = pooled @ W^T + b) + LayerNorm + ReLU ----------------
// BM=64, BN=256 (full row -> LN fused), BK=8, 256 threads, 8x8 per thread.
// warp ty owns rows {ty, ty+8, ..., ty+56}; lane tx owns cols {tx, tx+32, ...}.
__global__ void __launch_bounds__(256)
gemm_ln_kernel(const float* __restrict__ bias,
               const float* __restrict__ gamma,
               const float* __restrict__ beta,
               float* __restrict__ out)
{
    __shared__ __align__(16) float As[8][64];
    __shared__ __align__(16) float Bs[8][256];

    const int tid = threadIdx.x;
    const int tx = tid & 31, ty = tid >> 5;
    const int m0 = blockIdx.x * 64;

    float acc[8][8];
#pragma unroll
    for (int i = 0; i < 8; i++)
#pragma unroll
        for (int j = 0; j < 8; j++) acc[i][j] = 0.f;

    const int am = tid >> 3, ak = tid & 7;   // A-load mapping

    for (int kt = 0; kt < C_DIM; kt += 8) {
        As[ak][am]      = g_pooled[(m0 + am) * C_DIM + kt + ak];
        As[ak][am + 32] = g_pooled[(m0 + am + 32) * C_DIM + kt + ak];
        // B: thread (ty, tx) loads 8 consecutive floats of k-row (kt+ty)
        const float4 b0 = *(const float4*)&g_Wt[(kt + ty) * C_DIM + tx * 8];
        const float4 b1 = *(const float4*)&g_Wt[(kt + ty) * C_DIM + tx * 8 + 4];
        *(float4*)&Bs[ty][tx * 8]     = b0;
        *(float4*)&Bs[ty][tx * 8 + 4] = b1;
        __syncthreads();

#pragma unroll
        for (int k = 0; k < 8; k++) {
            float a[8], bb[8];
#pragma unroll
            for (int i = 0; i < 8; i++) a[i] = As[k][ty + 8 * i];   // warp broadcast
#pragma unroll
            for (int j = 0; j < 8; j++) bb[j] = Bs[k][tx + 32 * j]; // conflict-free
#pragma unroll
            for (int i = 0; i < 8; i++)
#pragma unroll
                for (int j = 0; j < 8; j++)
                    acc[i][j] = fmaf(a[i], bb[j], acc[i][j]);
        }
        __syncthreads();
    }

    // epilogue: bias + LayerNorm (warp = one row group) + ReLU
    float bv[8], gv[8], be[8];
#pragma unroll
    for (int j = 0; j < 8; j++) {
        int n = tx + 32 * j;
        bv[j] = bias[n]; gv[j] = gamma[n]; be[j] = beta[n];
    }
#pragma unroll
    for (int i = 0; i < 8; i++) {
        const int m = m0 + ty + 8 * i;
        float s = 0.f, ss = 0.f;
#pragma unroll
        for (int j = 0; j < 8; j++) {
            float v = acc[i][j] + bv[j];
            acc[i][j] = v;
            s += v;
            ss = fmaf(v, v, ss);
        }
#pragma unroll
        for (int off = 16; off; off >>= 1) {
            s  += __shfl_xor_sync(0xffffffffu, s,  off);
            ss += __shfl_xor_sync(0xffffffffu, ss, off);
        }
        const float mean = s * (1.f / 256.f);
        const float var  = ss * (1.f / 256.f) - mean * mean;
        const float rstd = rsqrtf(var + 1e-5f);
#pragma unroll
        for (int j = 0; j < 8; j++) {
            float v = (acc[i][j] - mean) * rstd * gv[j] + be[j];
            out[(size_t)m * C_DIM + tx + 32 * j] = fmaxf(v, 0.f);
        }
    }
}

// ---------------- launch ----------------
extern "C" void kernel_launch(void* const* d_in, const int* in_sizes, int n_in,
                              void* d_out, int out_size)
{
    const float* pts   = (const float*)d_in[0];
    // d_in[1] = src_masks (all true) -> ignored
    const float* feats = (const float*)d_in[2];
    const float* W     = (const float*)d_in[3];
    const float* bias  = (const float*)d_in[4];
    const float* gamma = (const float*)d_in[5];
    const float* beta  = (const float*)d_in[6];
    float* out = (float*)d_out;

    transpose_kernel<<<dim3(8, 8), dim3(32, 8)>>>(W);
    ball_query_kernel<<<N_PTS / QPB, 256>>>(pts);
    maxpool_kernel<<<N_PTS, 256>>>(feats);
    gemm_ln_kernel<<<N_PTS / 64, 256>>>(bias, gamma, beta, out);
}